// round 12
// baseline (speedup 1.0000x reference)
#include <cuda_runtime.h>
#include <cuda_fp16.h>
#include <cstdint>

// ---------------- problem constants ----------------
#define BTOT 7200      // bs*nq
#define N1   32768     // 2*E*D
#define N2   16384     // E*D
#define NS1  8         // k1 tile-range split (grid.y)  -> 904 GEMM blocks
#define NS2  4         // k2 d-split (grid.z)           -> 904 blocks

// ---------------- smem layout (bytes from dynamic base) ----------------
#define A_STRIDE 528               // 64 rows x 528B (256 fp16 + 16B pad)
#define B_OFF    33792             // A ends here
#define B_STRIDE 144               // 64 fp16 (128B) + 16B pad, conflict-free LDSM
#define CHUNK_B  18432             // 128 rows x 144B (one 64-K chunk)
#define SUPER_B  36864             // 2 chunks per super-stage
#define B_BYTES  73728             // 2 super-stages
#define MB_OFF   (B_OFF + B_BYTES)            // 107520
#define STG_OFF  (MB_OFF + 128)               // staging: 2 slots x 1024B
#define SMEM_12  (STG_OFF + 2048)             // 109696 -> 2 CTAs/SM (219KB/SM)
#define F3_OFF   (MB_OFF + 128)
#define SMEM_3K  (F3_OFF + 64*260*4)          // 174208 (k3, 1 CTA)

// ---------------- device scratch (allocation-free rule) ----------------
__device__ __half g_qh   [BTOT * 256];
__device__ __half g_wpreh[(size_t)N1 * 256];
__device__ __half g_wafth[(size_t)N2 * 256];
__device__ __half g_wouth[256 * 256];
__device__ float  g_f1p  [NS1 * BTOT * 64];   // k1 partials
__device__ float  g_f1n  [BTOT * 64];         // LN1 output
__device__ float  g_f2p  [NS2 * BTOT * 256];  // k2 partials per d-split

// ---------------- PTX helpers ----------------
__device__ __forceinline__ void mma_f16(float* c, const uint32_t* a, uint32_t b0, uint32_t b1) {
    asm volatile(
        "mma.sync.aligned.m16n8k16.row.col.f32.f16.f16.f32 "
        "{%0,%1,%2,%3}, {%4,%5,%6,%7}, {%8,%9}, {%0,%1,%2,%3};"
        : "+f"(c[0]), "+f"(c[1]), "+f"(c[2]), "+f"(c[3])
        : "r"(a[0]), "r"(a[1]), "r"(a[2]), "r"(a[3]), "r"(b0), "r"(b1));
}

__device__ __forceinline__ void ldsm4(uint32_t& r0, uint32_t& r1, uint32_t& r2, uint32_t& r3,
                                      uint32_t addr) {
    asm volatile("ldmatrix.sync.aligned.m8n8.x4.shared.b16 {%0,%1,%2,%3}, [%4];"
        : "=r"(r0), "=r"(r1), "=r"(r2), "=r"(r3) : "r"(addr));
}

__device__ __forceinline__ void cp16z(uint32_t s, const void* g, uint32_t sz) {
    asm volatile("cp.async.cg.shared.global [%0], [%1], 16, %2;" :: "r"(s), "l"(g), "r"(sz));
}
__device__ __forceinline__ void cp16(uint32_t s, const void* g) {
    asm volatile("cp.async.cg.shared.global [%0], [%1], 16;" :: "r"(s), "l"(g));
}
__device__ __forceinline__ void cp8z(uint32_t s, const void* g, uint32_t sz) {
    asm volatile("cp.async.ca.shared.global [%0], [%1], 8, %2;" :: "r"(s), "l"(g), "r"(sz));
}
__device__ __forceinline__ void cp4z(uint32_t s, const void* g, uint32_t sz) {
    asm volatile("cp.async.ca.shared.global [%0], [%1], 4, %2;" :: "r"(s), "l"(g), "r"(sz));
}
#define CP_COMMIT asm volatile("cp.async.commit_group;" ::: "memory")
#define CP_WAIT0  asm volatile("cp.async.wait_group 0;" ::: "memory")
#define CP_WAIT1  asm volatile("cp.async.wait_group 1;" ::: "memory")

__device__ __forceinline__ void mbar_init(uint32_t a, uint32_t c) {
    asm volatile("mbarrier.init.shared.b64 [%0], %1;" :: "r"(a), "r"(c) : "memory");
}
__device__ __forceinline__ void mbar_arrive(uint32_t a) {
    asm volatile("mbarrier.arrive.shared.b64 _, [%0];" :: "r"(a) : "memory");
}
__device__ __forceinline__ void mbar_wait(uint32_t a, uint32_t ph) {
    asm volatile(
        "{\n\t.reg .pred P;\n\t"
        "LW%=:\n\t"
        "mbarrier.try_wait.parity.acquire.cta.shared::cta.b64 P, [%0], %1, 0x989680;\n\t"
        "@P bra.uni LD%=;\n\t"
        "bra.uni LW%=;\n\t"
        "LD%=:\n\t}"
        :: "r"(a), "r"(ph) : "memory");
}

// ---------------- A tile load: 64 rows x 256 fp16 (tid<256) ----------------
__device__ __forceinline__ void load_A(uint32_t A, const __half* __restrict__ src,
                                       int m0, int tid) {
#pragma unroll
    for (int it = 0; it < 8; it++) {
        int idx = tid + it * 256;           // 0..2047
        int r = idx >> 5, c16 = idx & 31;
        uint32_t dst = A + r * A_STRIDE + c16 * 16;
        int gr = m0 + r;
        bool v = gr < BTOT;
        const __half* g = src + (v ? ((size_t)gr * 256 + c16 * 8) : 0);
        cp16z(dst, g, v ? 16u : 0u);
    }
    CP_COMMIT;
}

__device__ __forceinline__ void frag_addrs(uint32_t A, int wm, int wn, int lane,
                                           uint32_t& aaddr0, uint32_t& aaddr1, uint32_t& boff) {
    int a_row = ((lane >> 3) & 1) * 8 + (lane & 7);
    int a_cj  = lane >> 4;
    aaddr0 = A + (uint32_t)(wm * 32 + a_row) * A_STRIDE + (uint32_t)a_cj * 16;
    aaddr1 = aaddr0 + 16 * A_STRIDE;
    int b_row = (lane >> 4) * 8 + (lane & 7);
    int b_cj  = (lane >> 3) & 1;
    boff = (uint32_t)(wn * 32 + b_row) * B_STRIDE + (uint32_t)b_cj * 16;
}

// One 128-K super: 8 k16-steps, software-pipelined double-buffered fragments.
// Early empty-arrive: lane 0 arrives MBEs right after the LAST LDSM of the super.
__device__ __forceinline__ void super_mma(uint32_t aaddr0, uint32_t aaddr1, uint32_t Bsup,
                                          uint32_t boff, uint32_t kh, float cacc[2][4][4],
                                          uint32_t MBEs, int lane) {
    uint32_t a[2][2][4];
    uint32_t b[2][4][2];
    ldsm4(a[0][0][0], a[0][0][1], a[0][0][2], a[0][0][3], aaddr0 + kh);
    ldsm4(a[0][1][0], a[0][1][1], a[0][1][2], a[0][1][3], aaddr1 + kh);
    ldsm4(b[0][0][0], b[0][0][1], b[0][1][0], b[0][1][1], Bsup + boff);
    ldsm4(b[0][2][0], b[0][2][1], b[0][3][0], b[0][3][1], Bsup + boff + 16 * B_STRIDE);
#pragma unroll
    for (int j = 0; j < 8; j++) {
        const int cur = j & 1, nxt = cur ^ 1;
        if (j < 7) {
            const int jn = j + 1;
            const uint32_t ka = kh + (uint32_t)jn * 32;
            const uint32_t Bst = Bsup + (uint32_t)(jn >> 2) * CHUNK_B;
            const uint32_t kb = (uint32_t)(jn & 3) * 32;
            ldsm4(a[nxt][0][0], a[nxt][0][1], a[nxt][0][2], a[nxt][0][3], aaddr0 + ka);
            ldsm4(a[nxt][1][0], a[nxt][1][1], a[nxt][1][2], a[nxt][1][3], aaddr1 + ka);
            ldsm4(b[nxt][0][0], b[nxt][0][1], b[nxt][1][0], b[nxt][1][1], Bst + boff + kb);
            ldsm4(b[nxt][2][0], b[nxt][2][1], b[nxt][3][0], b[nxt][3][1],
                  Bst + boff + kb + 16 * B_STRIDE);
        } else {
            if (lane == 0) mbar_arrive(MBEs);   // all LDSM for this super done
        }
#pragma unroll
        for (int nf = 0; nf < 4; nf++) {
            mma_f16(cacc[0][nf], a[cur][0], b[cur][nf][0], b[cur][nf][1]);
            mma_f16(cacc[1][nf], a[cur][1], b[cur][nf][0], b[cur][nf][1]);
        }
    }
}

// Single-warp producer: one super-stage = 2 chunks, one commit group (k3 only).
__device__ __forceinline__ void issue_super(uint32_t B, int s, const __half* __restrict__ W,
                                            int koff, int lane) {
    uint32_t Bsup = B + (uint32_t)s * SUPER_B;
#pragma unroll
    for (int c = 0; c < 2; c++) {
        const __half* Wc = W + koff + c * 64;
        uint32_t Bst = Bsup + c * CHUNK_B;
#pragma unroll
        for (int i = 0; i < 32; i++) {
            int idx = i * 32 + lane;
            int row = idx >> 3, c16 = idx & 7;
            cp16(Bst + row * B_STRIDE + c16 * 16, Wc + (size_t)row * 256 + c16 * 8);
        }
    }
    CP_COMMIT;
}

// Dual-warp producer: this warp fills chunk pc (64-K) of super s. NO commit.
__device__ __forceinline__ void issue_chunk_nc(uint32_t B, int s, int pc,
                                               const __half* __restrict__ Wc, int lane) {
    uint32_t Bst = B + (uint32_t)s * SUPER_B + (uint32_t)pc * CHUNK_B;
#pragma unroll
    for (int i = 0; i < 32; i++) {
        int idx = i * 32 + lane;
        int row = idx >> 3, c16 = idx & 7;
        cp16(Bst + row * B_STRIDE + c16 * 16, Wc + (size_t)row * 256 + c16 * 8);
    }
}

#define ZERO_ACC(cacc) do { \
    _Pragma("unroll") for (int mi = 0; mi < 2; mi++) \
    _Pragma("unroll") for (int ni = 0; ni < 4; ni++) \
    _Pragma("unroll") for (int e = 0; e < 4; e++) cacc[mi][ni][e] = 0.f; } while (0)

__device__ __forceinline__ uint32_t pack_h2(float a, float b) {
    __half2 h = __floats2half2_rn(a, b);
    return *(uint32_t*)&h;
}

// ---------------- preround: Wpre + Q only (Waft/Wout folded into k1 tail) ----
__global__ void __launch_bounds__(256, 8) preround_kernel(
    const float* __restrict__ q, const float* __restrict__ wpre)
{
    size_t i = (size_t)blockIdx.x * 256 + threadIdx.x;   // float4 index
    const size_t S1 = (size_t)N1 * 64;
    const size_t S2 = S1 + (size_t)BTOT * 64;
    if (i >= S2) return;
    const float* src; __half* dst; size_t off;
    if (i < S1) { src = wpre; dst = g_wpreh; off = i; }
    else        { src = q;    dst = g_qh;    off = i - S1; }
    float4 v = ((const float4*)src)[off];
    ((__half2*)dst)[off * 2]     = __floats2half2_rn(v.x, v.y);
    ((__half2*)dst)[off * 2 + 1] = __floats2half2_rn(v.z, v.w);
}

// ---------------- Stage 1: super-staged, 2 producer warps + epilogue staging --
// grid (113, NS1+1): y<NS1 -> GEMM (32 tiles, 64 supers); y==NS1 -> convert Waft/Wout.
__global__ void __launch_bounds__(320, 2) k1_kernel(
    const float* __restrict__ feats, const float* __restrict__ bpre,
    const float* __restrict__ waft, const float* __restrict__ wout)
{
    const int tid = threadIdx.x, warp = tid >> 5, lane = tid & 31;

    if (blockIdx.y == NS1) {
        // ---- converter slice: runs in k1's tail wave ----
        const size_t T1 = (size_t)N2 * 64;            // waft float4s
        const size_t T2 = T1 + 256 * 64;              // + wout
        for (size_t i = (size_t)blockIdx.x * 320 + tid; i < T2; i += (size_t)113 * 320) {
            const float* src; __half* dst; size_t off;
            if (i < T1) { src = waft; dst = g_wafth; off = i; }
            else        { src = wout; dst = g_wouth; off = i - T1; }
            float4 v = ((const float4*)src)[off];
            ((__half2*)dst)[off * 2]     = __floats2half2_rn(v.x, v.y);
            ((__half2*)dst)[off * 2 + 1] = __floats2half2_rn(v.z, v.w);
        }
        return;
    }

    extern __shared__ unsigned char sm[];
    uint32_t sb = (uint32_t)__cvta_generic_to_shared(sm);
    const uint32_t A = sb, B = sb + B_OFF;
    const uint32_t MBF = sb + MB_OFF, MBE = sb + MB_OFF + 16;
    const uint32_t STG = sb + STG_OFF;

    const int m0 = blockIdx.x * 64;
    const int nt0 = blockIdx.y * 32;
    const int G = 64;    // 32 tiles x 2 supers

    if (tid == 0) {
        mbar_init(MBF, 64); mbar_init(MBF + 8, 64);   // 2 producer warps x 32 lanes
        mbar_init(MBE, 8);  mbar_init(MBE + 8, 8);
    }
    if (tid < 256) { load_A(A, g_qh, m0, tid); CP_WAIT0; }
    __syncthreads();

    float freg[2][4][4];
    ZERO_ACC(freg);
    const int wm = warp >> 2, wn = warp & 3;
    const int gID = lane >> 2, t4 = lane & 3;
    const int h = wn >> 1;

    if (warp >= 8) {
        // ---- producers: warp 8 fills chunk 0 (+bias staging), warp 9 chunk 1 (+feats) --
        const int pc = warp - 8;
        for (int g = 0; g < G; g++) {
            int s = g & 1;
            if (g >= 2) mbar_wait(MBE + s * 8, ((g >> 1) - 1) & 1);
            const int t = g >> 1;
            const int p0 = (nt0 + t) << 7;
            const __half* Wc = g_wpreh + (size_t)p0 * 256 + (g & 1) * 128 + pc * 64;
            issue_chunk_nc(B, s, pc, Wc, lane);
            if ((g & 1) == 0) {
                // epilogue staging for tile t into slot t&1
                uint32_t stg = STG + (uint32_t)(t & 1) * 1024;
                if (pc == 0) {
                    cp16(stg + lane * 16, bpre + p0 + lane * 4);             // 128 bias floats
                } else {
                    const int kf = p0 >> 6;
#pragma unroll
                    for (int jj = 0; jj < 2; jj++) {
                        int r = jj * 32 + lane;
                        int b = m0 + r;
                        cp8z(stg + 512 + r * 8,
                             feats + (b < BTOT ? ((size_t)b * 512 + kf) : 0),
                             (b < BTOT) ? 8u : 0u);                          // feats[kf], [kf+1]
                    }
                }
            }
            CP_COMMIT;
            if (g >= 1) { CP_WAIT1; mbar_arrive(MBF + ((g - 1) & 1) * 8); }
        }
        CP_WAIT0; mbar_arrive(MBF + ((G - 1) & 1) * 8);
    } else {
        uint32_t aaddr0, aaddr1, boff;
        frag_addrs(A, wm, wn, lane, aaddr0, aaddr1, boff);
        float cacc[2][4][4];
        ZERO_ACC(cacc);
        for (int g = 0; g < G; g++) {
            int s = g & 1;
            mbar_wait(MBF + s * 8, (g >> 1) & 1);
            super_mma(aaddr0, aaddr1, B + (uint32_t)s * SUPER_B, boff,
                      (uint32_t)(g & 1) * 256, cacc, MBE + s * 8, lane);
            if (g & 1) {
                const int t = g >> 1;
                const float* stg = (const float*)(sm + STG_OFF + (t & 1) * 1024);
                const float* stg_fv = stg + 128;
                float fv[2][2];
#pragma unroll
                for (int mi = 0; mi < 2; mi++)
#pragma unroll
                    for (int eh = 0; eh < 2; eh++) {
                        int row = wm * 32 + mi * 16 + gID + (eh << 3);
                        fv[mi][eh] = stg_fv[row * 2 + h];
                    }
#pragma unroll
                for (int ni = 0; ni < 4; ni++) {
                    int colb = wn * 32 + ni * 8 + t4 * 2;
                    float2 bb = *(const float2*)(stg + colb);
#pragma unroll
                    for (int mi = 0; mi < 2; mi++)
#pragma unroll
                        for (int e = 0; e < 4; e++) {
                            float bias = (e & 1) ? bb.y : bb.x;
                            freg[mi][ni][e] += fv[mi][e >> 1] * (cacc[mi][ni][e] + bias);
                        }
                }
                ZERO_ACC(cacc);
            }
        }
    }

    // ---- cross-warp reduction via overlaid smem buffer ----
    __syncthreads();
    float* f1a = (float*)(sm + B_OFF);
    for (int i = tid; i < 64 * 65; i += 320) f1a[i] = 0.f;
    __syncthreads();
    if (warp < 8) {
#pragma unroll
        for (int mi = 0; mi < 2; mi++)
#pragma unroll
            for (int ni = 0; ni < 4; ni++)
#pragma unroll
                for (int e = 0; e < 4; e++) {
                    int row = wm * 32 + mi * 16 + gID + ((e >> 1) << 3);
                    int col = wn * 32 + ni * 8 + t4 * 2 + (e & 1);
                    atomicAdd(&f1a[row * 65 + (col & 63)], freg[mi][ni][e]);
                }
    }
    __syncthreads();

    float* dst = g_f1p + (size_t)blockIdx.y * (BTOT * 64);
    for (int i = tid; i < 64 * 64; i += 320) {
        int r = i >> 6, d = i & 63;
        int b = m0 + r;
        if (b < BTOT) dst[(size_t)b * 64 + d] = f1a[r * 65 + d];
    }
}

// ---------------- LN1: sum NS1 partials, LayerNorm(64)+relu ----------------
__global__ void __launch_bounds__(256, 8) ln1_kernel(
    const float* __restrict__ g1, const float* __restrict__ be1)
{
    int w = threadIdx.x >> 5, lane = threadIdx.x & 31;
    int b = blockIdx.x * 8 + w;
    if (b >= BTOT) return;
    int d = lane * 2;
    float v0 = 0.f, v1 = 0.f;
#pragma unroll
    for (int s = 0; s < NS1; s++) {
        float2 t = *(const float2*)(g_f1p + (size_t)s * (BTOT * 64) + (size_t)b * 64 + d);
        v0 += t.x; v1 += t.y;
    }
    float s1 = v0 + v1, s2 = v0 * v0 + v1 * v1;
#pragma unroll
    for (int o = 16; o; o >>= 1) {
        s1 += __shfl_xor_sync(0xffffffffu, s1, o);
        s2 += __shfl_xor_sync(0xffffffffu, s2, o);
    }
    float mu = s1 * (1.f / 64.f);
    float inv = rsqrtf(s2 * (1.f / 64.f) - mu * mu + 1e-5f);
    float y0 = fmaxf((v0 - mu) * inv * g1[d] + be1[d], 0.f);
    float y1 = fmaxf((v1 - mu) * inv * g1[d + 1] + be1[d + 1], 0.f);
    *(float2*)(g_f1n + (size_t)b * 64 + d) = make_float2(y0, y1);
}

// ---------------- Stage 2: super-staged, 2 producer warps + epilogue staging --
// grid (113, 2, NS2): each block does 16 d's -> 32 supers.
__global__ void __launch_bounds__(320, 2) k2_kernel(const float* __restrict__ baft)
{
    extern __shared__ unsigned char sm[];
    uint32_t sb = (uint32_t)__cvta_generic_to_shared(sm);
    const uint32_t A = sb, B = sb + B_OFF;
    const uint32_t MBF = sb + MB_OFF, MBE = sb + MB_OFF + 16;
    const uint32_t STG = sb + STG_OFF;

    const int tid = threadIdx.x, warp = tid >> 5, lane = tid & 31;
    const int m0 = blockIdx.x * 64;
    const int e0 = blockIdx.y << 7;
    const int d0 = blockIdx.z << 4;       // 16 d's per block
    const int G = 32;                     // 16 tiles x 2 supers

    if (tid == 0) {
        mbar_init(MBF, 64); mbar_init(MBF + 8, 64);
        mbar_init(MBE, 8);  mbar_init(MBE + 8, 8);
    }
    if (tid < 256) { load_A(A, g_qh, m0, tid); CP_WAIT0; }
    __syncthreads();

    const int wm = warp >> 2, wn = warp & 3;
    const int gID = lane >> 2, t4 = lane & 3;

    if (warp >= 8) {
        const int pc = warp - 8;
        for (int g = 0; g < G; g++) {
            int s = g & 1;
            if (g >= 2) mbar_wait(MBE + s * 8, ((g >> 1) - 1) & 1);
            const int t = g >> 1;
            const int d = d0 + t;
            const int p0 = (d << 8) + e0;
            const __half* Wc = g_wafth + (size_t)p0 * 256 + (g & 1) * 128 + pc * 64;
            issue_chunk_nc(B, s, pc, Wc, lane);
            if ((g & 1) == 0) {
                uint32_t stg = STG + (uint32_t)(t & 1) * 1024;
                if (pc == 0) {
                    cp16(stg + lane * 16, baft + p0 + lane * 4);             // 128 bias floats
                } else {
#pragma unroll
                    for (int jj = 0; jj < 2; jj++) {
                        int r = jj * 32 + lane;
                        int b = m0 + r;
                        cp4z(stg + 512 + r * 4,
                             g_f1n + (b < BTOT ? ((size_t)b * 64 + d) : 0),
                             (b < BTOT) ? 4u : 0u);                          // f1n column
                    }
                }
            }
            CP_COMMIT;
            if (g >= 1) { CP_WAIT1; mbar_arrive(MBF + ((g - 1) & 1) * 8); }
        }
        CP_WAIT0; mbar_arrive(MBF + ((G - 1) & 1) * 8);
    } else {
        uint32_t aaddr0, aaddr1, boff;
        frag_addrs(A, wm, wn, lane, aaddr0, aaddr1, boff);
        float facc[2][4][4];
        ZERO_ACC(facc);
        float cacc[2][4][4];
        ZERO_ACC(cacc);
        for (int g = 0; g < G; g++) {
            int s = g & 1;
            mbar_wait(MBF + s * 8, (g >> 1) & 1);
            super_mma(aaddr0, aaddr1, B + (uint32_t)s * SUPER_B, boff,
                      (uint32_t)(g & 1) * 256, cacc, MBE + s * 8, lane);
            if (g & 1) {
                const int t = g >> 1;
                const float* stg = (const float*)(sm + STG_OFF + (t & 1) * 1024);
                const float* stg_fv = stg + 128;
                float fv[2][2];
#pragma unroll
                for (int mi = 0; mi < 2; mi++)
#pragma unroll
                    for (int eh = 0; eh < 2; eh++) {
                        int row = wm * 32 + mi * 16 + gID + (eh << 3);
                        fv[mi][eh] = stg_fv[row];
                    }
#pragma unroll
                for (int ni = 0; ni < 4; ni++) {
                    int colb = wn * 32 + ni * 8 + t4 * 2;
                    float2 bb = *(const float2*)(stg + colb);
#pragma unroll
                    for (int mi = 0; mi < 2; mi++)
#pragma unroll
                        for (int e = 0; e < 4; e++) {
                            float bias = (e & 1) ? bb.y : bb.x;
                            facc[mi][ni][e] += fv[mi][e >> 1] * (cacc[mi][ni][e] + bias);
                        }
                }
                ZERO_ACC(cacc);
            }
        }
        float* dst = g_f2p + (size_t)blockIdx.z * (BTOT * 256);
#pragma unroll
        for (int mi = 0; mi < 2; mi++)
#pragma unroll
            for (int ni = 0; ni < 4; ni++)
#pragma unroll
                for (int e = 0; e < 4; e++) {
                    int row = wm * 32 + mi * 16 + gID + ((e >> 1) << 3);
                    int col = wn * 32 + ni * 8 + t4 * 2 + (e & 1);
                    int b = m0 + row;
                    if (b < BTOT) dst[(size_t)b * 256 + e0 + col] = facc[mi][ni][e];
                }
    }
}

// ---------------- Stage 3: fused LN2 (A-fill) + GEMM + LN3 ----------------
__global__ void __launch_bounds__(320, 1) k3_kernel(
    const float* __restrict__ g2, const float* __restrict__ be2,
    const float* __restrict__ bout,
    const float* __restrict__ g3, const float* __restrict__ be3,
    float* __restrict__ out)
{
    extern __shared__ unsigned char sm[];
    uint32_t sb = (uint32_t)__cvta_generic_to_shared(sm);
    const uint32_t A = sb, B = sb + B_OFF;
    const uint32_t MBF = sb + MB_OFF, MBE = sb + MB_OFF + 16;
    float* f3a = (float*)(sm + F3_OFF);

    const int tid = threadIdx.x, warp = tid >> 5, lane = tid & 31;
    const int m0 = blockIdx.x * 64;
    const int G = 4;     // 2 tiles x 2 supers

    if (tid == 0) {
        mbar_init(MBF, 32); mbar_init(MBF + 8, 32);   // single producer warp
        mbar_init(MBE, 8);  mbar_init(MBE + 8, 8);
    }

    // ---- fused LN2: sum NS2 partials -> LN -> fp16 -> A smem ----
    if (warp < 8) {
#pragma unroll
        for (int j = 0; j < 8; j++) {
            int r = warp * 8 + j;
            int b = m0 + r;
            float v[8];
#pragma unroll
            for (int i = 0; i < 8; i++) v[i] = 0.f;
            if (b < BTOT) {
#pragma unroll
                for (int sp = 0; sp < NS2; sp++) {
                    const float4* p = (const float4*)(g_f2p + (size_t)sp * (BTOT * 256)
                                                      + (size_t)b * 256 + lane * 8);
                    float4 x0 = p[0], x1 = p[1];
                    v[0] += x0.x; v[1] += x0.y; v[2] += x0.z; v[3] += x0.w;
                    v[4] += x1.x; v[5] += x1.y; v[6] += x1.z; v[7] += x1.w;
                }
            }
            float s1 = 0.f, s2 = 0.f;
#pragma unroll
            for (int i = 0; i < 8; i++) { s1 += v[i]; s2 += v[i] * v[i]; }
#pragma unroll
            for (int o = 16; o; o >>= 1) {
                s1 += __shfl_xor_sync(0xffffffffu, s1, o);
                s2 += __shfl_xor_sync(0xffffffffu, s2, o);
            }
            float mu = s1 * (1.f / 256.f);
            float inv = rsqrtf(s2 * (1.f / 256.f) - mu * mu + 1e-5f);
            float o_[8];
#pragma unroll
            for (int i = 0; i < 8; i++) {
                int e = lane * 8 + i;
                o_[i] = fmaxf((v[i] - mu) * inv * g2[e] + be2[e], 0.f);
            }
            uint4 pk;
            pk.x = pack_h2(o_[0], o_[1]); pk.y = pack_h2(o_[2], o_[3]);
            pk.z = pack_h2(o_[4], o_[5]); pk.w = pack_h2(o_[6], o_[7]);
            *(uint4*)(sm + r * A_STRIDE + lane * 16) = pk;
        }
    }
    __syncthreads();

    const int wm = warp >> 2, wn = warp & 3;
    const int gID = lane >> 2, t4 = lane & 3;

    if (warp == 8) {
        for (int g = 0; g < G; g++) {
            int s = g & 1;
            if (g >= 2) mbar_wait(MBE + s * 8, ((g >> 1) - 1) & 1);
            int p0 = (g >> 1) << 7;
            issue_super(B, s, g_wouth + (size_t)p0 * 256, (g & 1) * 128, lane);
            if (g >= 1) { CP_WAIT1; mbar_arrive(MBF + ((g - 1) & 1) * 8); }
        }
        CP_WAIT0; mbar_arrive(MBF + ((G - 1) & 1) * 8);
    } else if (warp < 8) {
        uint32_t aaddr0, aaddr1, boff;
        frag_addrs(A, wm, wn, lane, aaddr0, aaddr1, boff);
        float cacc[2][4][4];
        ZERO_ACC(cacc);
        for (int g = 0; g < G; g++) {
            int s = g & 1;
            mbar_wait(MBF + s * 8, (g >> 1) & 1);
            super_mma(aaddr0, aaddr1, B + (uint32_t)s * SUPER_B, boff,
                      (uint32_t)(g & 1) * 256, cacc, MBE + s * 8, lane);
            if (g & 1) {
                const int p0 = (g >> 1) << 7;
#pragma unroll
                for (int mi = 0; mi < 2; mi++)
#pragma unroll
                    for (int ni = 0; ni < 4; ni++)
#pragma unroll
                        for (int e = 0; e < 4; e++) {
                            int row = wm * 32 + mi * 16 + gID + ((e >> 1) << 3);
                            int col = wn * 32 + ni * 8 + t4 * 2 + (e & 1);
                            f3a[row * 260 + p0 + col] = cacc[mi][ni][e] + __ldg(&bout[p0 + col]);
                        }
                ZERO_ACC(cacc);
            }
        }
    }
    __syncthreads();

    if (tid < 256) {
        const int row = tid >> 2;
        const int b = m0 + row;
        if (b < BTOT) {
            const int e0 = (tid & 3) * 64;
            float s1 = 0.f, s2 = 0.f;
#pragma unroll
            for (int i = 0; i < 64; i++) {
                float x = f3a[row * 260 + e0 + i];
                s1 += x; s2 += x * x;
            }
            s1 += __shfl_xor_sync(0xffffffffu, s1, 1); s1 += __shfl_xor_sync(0xffffffffu, s1, 2);
            s2 += __shfl_xor_sync(0xffffffffu, s2, 1); s2 += __shfl_xor_sync(0xffffffffu, s2, 2);
            float mu = s1 * (1.f / 256.f);
            float inv = rsqrtf(s2 * (1.f / 256.f) - mu * mu + 1e-5f);
#pragma unroll
            for (int i = 0; i < 64; i++) {
                int e = e0 + i;
                float y = (f3a[row * 260 + e] - mu) * inv * g3[e] + be3[e];
                out[(size_t)b * 256 + e] = fmaxf(y, 0.f);
            }
        }
    }
}

// ---------------- host launch ----------------
extern "C" void kernel_launch(void* const* d_in, const int* in_sizes, int n_in,
                              void* d_out, int out_size)
{
    const float* q     = (const float*)d_in[0];
    const float* feats = (const float*)d_in[1];
    const float* Wpre  = (const float*)d_in[2];
    const float* bpre  = (const float*)d_in[3];
    const float* Waft  = (const float*)d_in[4];
    const float* baft  = (const float*)d_in[5];
    const float* Wout  = (const float*)d_in[6];
    const float* bout  = (const float*)d_in[7];
    const float* g1  = (const float*)d_in[8];
    const float* be1 = (const float*)d_in[9];
    const float* g2  = (const float*)d_in[10];
    const float* be2 = (const float*)d_in[11];
    const float* g3  = (const float*)d_in[12];
    const float* be3 = (const float*)d_in[13];
    float* out = (float*)d_out;

    cudaFuncSetAttribute(k1_kernel, cudaFuncAttributeMaxDynamicSharedMemorySize, SMEM_12);
    cudaFuncSetAttribute(k2_kernel, cudaFuncAttributeMaxDynamicSharedMemorySize, SMEM_12);
    cudaFuncSetAttribute(k3_kernel, cudaFuncAttributeMaxDynamicSharedMemorySize, SMEM_3K);

    // preround: Wpre + Q only
    const size_t nf4 = (size_t)N1 * 64 + (size_t)BTOT * 64;
    int pr_blocks = (int)((nf4 + 255) / 256);

    preround_kernel<<<pr_blocks, 256>>>(q, Wpre);
    k1_kernel<<<dim3(113, NS1 + 1), 320, SMEM_12>>>(feats, bpre, Waft, Wout);
    ln1_kernel<<<dim3(900), 256>>>(g1, be1);
    k2_kernel<<<dim3(113, 2, NS2), 320, SMEM_12>>>(baft);
    k3_kernel<<<dim3(113), 320, SMEM_3K>>>(g2, be2, bout, g3, be3, out);
}

// round 13
// speedup vs baseline: 1.0416x; 1.0416x over previous
#include <cuda_runtime.h>
#include <cuda_fp16.h>
#include <cstdint>

// ---------------- problem constants ----------------
#define BTOT 7200      // bs*nq
#define N1   32768     // 2*E*D
#define N2   16384     // E*D
#define NS1  8         // k1 tile-range split (grid.y)  -> 904 GEMM blocks
#define NS2  4         // k2 d-split (grid.z)           -> 904 blocks

// ---------------- smem layout (bytes from dynamic base) ----------------
#define A_STRIDE 528               // 64 rows x 528B (256 fp16 + 16B pad)
#define B_OFF    33792             // A ends here
#define B_STRIDE 144               // 64 fp16 (128B) + 16B pad, conflict-free LDSM
#define CHUNK_B  18432             // 128 rows x 144B (one 64-K chunk)
#define SUPER_B  36864             // 2 chunks per super-stage
#define B_BYTES  73728             // 2 super-stages
#define MB_OFF   (B_OFF + B_BYTES)            // 107520
#define SMEM_12  (MB_OFF + 128)               // 107648 -> 2 CTAs/SM
#define F3_OFF   (MB_OFF + 128)
#define SMEM_3K  (F3_OFF + 64*260*4)          // 174208 (k3, 1 CTA)

// ---------------- device scratch (allocation-free rule) ----------------
__device__ __half g_qh   [BTOT * 256];
__device__ __half g_wpreh[(size_t)N1 * 256];
__device__ __half g_wafth[(size_t)N2 * 256];
__device__ __half g_wouth[256 * 256];
__device__ float  g_f1p  [NS1 * BTOT * 64];   // k1 partials
__device__ float  g_f1n  [BTOT * 64];         // LN1 output
__device__ float  g_f2p  [NS2 * BTOT * 256];  // k2 partials per d-split

// ---------------- PTX helpers ----------------
__device__ __forceinline__ void mma_f16(float* c, const uint32_t* a, uint32_t b0, uint32_t b1) {
    asm volatile(
        "mma.sync.aligned.m16n8k16.row.col.f32.f16.f16.f32 "
        "{%0,%1,%2,%3}, {%4,%5,%6,%7}, {%8,%9}, {%0,%1,%2,%3};"
        : "+f"(c[0]), "+f"(c[1]), "+f"(c[2]), "+f"(c[3])
        : "r"(a[0]), "r"(a[1]), "r"(a[2]), "r"(a[3]), "r"(b0), "r"(b1));
}

__device__ __forceinline__ void ldsm4(uint32_t& r0, uint32_t& r1, uint32_t& r2, uint32_t& r3,
                                      uint32_t addr) {
    asm volatile("ldmatrix.sync.aligned.m8n8.x4.shared.b16 {%0,%1,%2,%3}, [%4];"
        : "=r"(r0), "=r"(r1), "=r"(r2), "=r"(r3) : "r"(addr));
}

__device__ __forceinline__ void cp16z(uint32_t s, const void* g, uint32_t sz) {
    asm volatile("cp.async.cg.shared.global [%0], [%1], 16, %2;" :: "r"(s), "l"(g), "r"(sz));
}
__device__ __forceinline__ void cp16(uint32_t s, const void* g) {
    asm volatile("cp.async.cg.shared.global [%0], [%1], 16;" :: "r"(s), "l"(g));
}
#define CP_COMMIT asm volatile("cp.async.commit_group;" ::: "memory")
#define CP_WAIT0  asm volatile("cp.async.wait_group 0;" ::: "memory")
#define CP_WAIT1  asm volatile("cp.async.wait_group 1;" ::: "memory")

__device__ __forceinline__ void mbar_init(uint32_t a, uint32_t c) {
    asm volatile("mbarrier.init.shared.b64 [%0], %1;" :: "r"(a), "r"(c) : "memory");
}
__device__ __forceinline__ void mbar_arrive(uint32_t a) {
    asm volatile("mbarrier.arrive.shared.b64 _, [%0];" :: "r"(a) : "memory");
}
__device__ __forceinline__ void mbar_wait(uint32_t a, uint32_t ph) {
    asm volatile(
        "{\n\t.reg .pred P;\n\t"
        "LW%=:\n\t"
        "mbarrier.try_wait.parity.acquire.cta.shared::cta.b64 P, [%0], %1, 0x989680;\n\t"
        "@P bra.uni LD%=;\n\t"
        "bra.uni LW%=;\n\t"
        "LD%=:\n\t}"
        :: "r"(a), "r"(ph) : "memory");
}

// ---------------- A tile load: 64 rows x 256 fp16 (tid<256) ----------------
__device__ __forceinline__ void load_A(uint32_t A, const __half* __restrict__ src,
                                       int m0, int tid) {
#pragma unroll
    for (int it = 0; it < 8; it++) {
        int idx = tid + it * 256;           // 0..2047
        int r = idx >> 5, c16 = idx & 31;
        uint32_t dst = A + r * A_STRIDE + c16 * 16;
        int gr = m0 + r;
        bool v = gr < BTOT;
        const __half* g = src + (v ? ((size_t)gr * 256 + c16 * 8) : 0);
        cp16z(dst, g, v ? 16u : 0u);
    }
    CP_COMMIT;
}

__device__ __forceinline__ void frag_addrs(uint32_t A, int wm, int wn, int lane,
                                           uint32_t& aaddr0, uint32_t& aaddr1, uint32_t& boff) {
    int a_row = ((lane >> 3) & 1) * 8 + (lane & 7);
    int a_cj  = lane >> 4;
    aaddr0 = A + (uint32_t)(wm * 32 + a_row) * A_STRIDE + (uint32_t)a_cj * 16;
    aaddr1 = aaddr0 + 16 * A_STRIDE;
    int b_row = (lane >> 4) * 8 + (lane & 7);
    int b_cj  = (lane >> 3) & 1;
    boff = (uint32_t)(wn * 32 + b_row) * B_STRIDE + (uint32_t)b_cj * 16;
}

// One 128-K super: 8 k16-steps, software-pipelined double-buffered fragments.
// Early empty-arrive: lane 0 arrives MBEs right after the LAST LDSM of the super.
__device__ __forceinline__ void super_mma(uint32_t aaddr0, uint32_t aaddr1, uint32_t Bsup,
                                          uint32_t boff, uint32_t kh, float cacc[2][4][4],
                                          uint32_t MBEs, int lane) {
    uint32_t a[2][2][4];
    uint32_t b[2][4][2];
    ldsm4(a[0][0][0], a[0][0][1], a[0][0][2], a[0][0][3], aaddr0 + kh);
    ldsm4(a[0][1][0], a[0][1][1], a[0][1][2], a[0][1][3], aaddr1 + kh);
    ldsm4(b[0][0][0], b[0][0][1], b[0][1][0], b[0][1][1], Bsup + boff);
    ldsm4(b[0][2][0], b[0][2][1], b[0][3][0], b[0][3][1], Bsup + boff + 16 * B_STRIDE);
#pragma unroll
    for (int j = 0; j < 8; j++) {
        const int cur = j & 1, nxt = cur ^ 1;
        if (j < 7) {
            const int jn = j + 1;
            const uint32_t ka = kh + (uint32_t)jn * 32;
            const uint32_t Bst = Bsup + (uint32_t)(jn >> 2) * CHUNK_B;
            const uint32_t kb = (uint32_t)(jn & 3) * 32;
            ldsm4(a[nxt][0][0], a[nxt][0][1], a[nxt][0][2], a[nxt][0][3], aaddr0 + ka);
            ldsm4(a[nxt][1][0], a[nxt][1][1], a[nxt][1][2], a[nxt][1][3], aaddr1 + ka);
            ldsm4(b[nxt][0][0], b[nxt][0][1], b[nxt][1][0], b[nxt][1][1], Bst + boff + kb);
            ldsm4(b[nxt][2][0], b[nxt][2][1], b[nxt][3][0], b[nxt][3][1],
                  Bst + boff + kb + 16 * B_STRIDE);
        } else {
            if (lane == 0) mbar_arrive(MBEs);   // all LDSM for this super done
        }
#pragma unroll
        for (int nf = 0; nf < 4; nf++) {
            mma_f16(cacc[0][nf], a[cur][0], b[cur][nf][0], b[cur][nf][1]);
            mma_f16(cacc[1][nf], a[cur][1], b[cur][nf][0], b[cur][nf][1]);
        }
    }
}

// Dual-warp producer: this warp fills chunk pc (64-K) of super s, own commit group.
__device__ __forceinline__ void issue_chunk_p(uint32_t B, int s, int pc,
                                              const __half* __restrict__ Wc, int lane) {
    uint32_t Bst = B + (uint32_t)s * SUPER_B + (uint32_t)pc * CHUNK_B;
#pragma unroll
    for (int i = 0; i < 32; i++) {
        int idx = i * 32 + lane;
        int row = idx >> 3, c16 = idx & 7;
        cp16(Bst + row * B_STRIDE + c16 * 16, Wc + (size_t)row * 256 + c16 * 8);
    }
    CP_COMMIT;
}

#define ZERO_ACC(cacc) do { \
    _Pragma("unroll") for (int mi = 0; mi < 2; mi++) \
    _Pragma("unroll") for (int ni = 0; ni < 4; ni++) \
    _Pragma("unroll") for (int e = 0; e < 4; e++) cacc[mi][ni][e] = 0.f; } while (0)

__device__ __forceinline__ uint32_t pack_h2(float a, float b) {
    __half2 h = __floats2half2_rn(a, b);
    return *(uint32_t*)&h;
}

// ---------------- preround: Wpre + Q only (Waft/Wout folded into k1 tail) ----
__global__ void __launch_bounds__(256, 8) preround_kernel(
    const float* __restrict__ q, const float* __restrict__ wpre)
{
    size_t i = (size_t)blockIdx.x * 256 + threadIdx.x;   // float4 index
    const size_t S1 = (size_t)N1 * 64;
    const size_t S2 = S1 + (size_t)BTOT * 64;
    if (i >= S2) return;
    const float* src; __half* dst; size_t off;
    if (i < S1) { src = wpre; dst = g_wpreh; off = i; }
    else        { src = q;    dst = g_qh;    off = i - S1; }
    float4 v = ((const float4*)src)[off];
    ((__half2*)dst)[off * 2]     = __floats2half2_rn(v.x, v.y);
    ((__half2*)dst)[off * 2 + 1] = __floats2half2_rn(v.z, v.w);
}

// ---------------- Stage 1: super-staged, 2 producer warps ----------------
// grid (113, NS1+1): y<NS1 -> GEMM (32 tiles, 64 supers); y==NS1 -> convert Waft/Wout.
__global__ void __launch_bounds__(320, 2) k1_kernel(
    const float* __restrict__ feats, const float* __restrict__ bpre,
    const float* __restrict__ waft, const float* __restrict__ wout)
{
    const int tid = threadIdx.x, warp = tid >> 5, lane = tid & 31;

    if (blockIdx.y == NS1) {
        // ---- converter slice: runs in k1's tail wave ----
        const size_t T1 = (size_t)N2 * 64;            // waft float4s
        const size_t T2 = T1 + 256 * 64;              // + wout
        for (size_t i = (size_t)blockIdx.x * 320 + tid; i < T2; i += (size_t)113 * 320) {
            const float* src; __half* dst; size_t off;
            if (i < T1) { src = waft; dst = g_wafth; off = i; }
            else        { src = wout; dst = g_wouth; off = i - T1; }
            float4 v = ((const float4*)src)[off];
            ((__half2*)dst)[off * 2]     = __floats2half2_rn(v.x, v.y);
            ((__half2*)dst)[off * 2 + 1] = __floats2half2_rn(v.z, v.w);
        }
        return;
    }

    extern __shared__ unsigned char sm[];
    uint32_t sb = (uint32_t)__cvta_generic_to_shared(sm);
    const uint32_t A = sb, B = sb + B_OFF;
    const uint32_t MBF = sb + MB_OFF, MBE = sb + MB_OFF + 16;

    const int m0 = blockIdx.x * 64;
    const int nt0 = blockIdx.y * 32;
    const int G = 64;    // 32 tiles x 2 supers

    if (tid == 0) {
        mbar_init(MBF, 64); mbar_init(MBF + 8, 64);   // 2 producer warps x 32 lanes
        mbar_init(MBE, 8);  mbar_init(MBE + 8, 8);
    }
    if (tid < 256) { load_A(A, g_qh, m0, tid); CP_WAIT0; }
    __syncthreads();

    float freg[2][4][4];
    ZERO_ACC(freg);
    const int wm = warp >> 2, wn = warp & 3;
    const int gID = lane >> 2, t4 = lane & 3;
    const int h = wn >> 1;

    if (warp >= 8) {
        // ---- producers: warp 8 fills chunk 0, warp 9 fills chunk 1 ----
        const int pc = warp - 8;
        for (int g = 0; g < G; g++) {
            int s = g & 1;
            if (g >= 2) mbar_wait(MBE + s * 8, ((g >> 1) - 1) & 1);
            const __half* Wc = g_wpreh + ((size_t)((nt0 + (g >> 1)) << 7)) * 256
                             + (g & 1) * 128 + pc * 64;
            issue_chunk_p(B, s, pc, Wc, lane);
            if (g >= 1) { CP_WAIT1; mbar_arrive(MBF + ((g - 1) & 1) * 8); }
        }
        CP_WAIT0; mbar_arrive(MBF + ((G - 1) & 1) * 8);
    } else {
        uint32_t aaddr0, aaddr1, boff;
        frag_addrs(A, wm, wn, lane, aaddr0, aaddr1, boff);
        float cacc[2][4][4];
        ZERO_ACC(cacc);
        for (int g = 0; g < G; g++) {
            int s = g & 1;
            mbar_wait(MBF + s * 8, (g >> 1) & 1);
            super_mma(aaddr0, aaddr1, B + (uint32_t)s * SUPER_B, boff,
                      (uint32_t)(g & 1) * 256, cacc, MBE + s * 8, lane);
            if (g & 1) {
                const int t = g >> 1;
                const int p0 = (nt0 + t) << 7;
                const int kf = p0 >> 6;
                float fv[2][2];
#pragma unroll
                for (int mi = 0; mi < 2; mi++)
#pragma unroll
                    for (int eh = 0; eh < 2; eh++) {
                        int b = m0 + wm * 32 + mi * 16 + gID + (eh << 3);
                        fv[mi][eh] = (b < BTOT) ? __ldg(&feats[(size_t)b * 512 + kf + h]) : 0.f;
                    }
#pragma unroll
                for (int ni = 0; ni < 4; ni++) {
                    int colb = wn * 32 + ni * 8 + t4 * 2;
                    float b0 = __ldg(&bpre[p0 + colb]);
                    float b1 = __ldg(&bpre[p0 + colb + 1]);
#pragma unroll
                    for (int mi = 0; mi < 2; mi++)
#pragma unroll
                        for (int e = 0; e < 4; e++) {
                            float bias = (e & 1) ? b1 : b0;
                            freg[mi][ni][e] += fv[mi][e >> 1] * (cacc[mi][ni][e] + bias);
                        }
                }
                ZERO_ACC(cacc);
            }
        }
    }

    // ---- cross-warp reduction via overlaid smem buffer ----
    __syncthreads();
    float* f1a = (float*)(sm + B_OFF);
    for (int i = tid; i < 64 * 65; i += 320) f1a[i] = 0.f;
    __syncthreads();
    if (warp < 8) {
#pragma unroll
        for (int mi = 0; mi < 2; mi++)
#pragma unroll
            for (int ni = 0; ni < 4; ni++)
#pragma unroll
                for (int e = 0; e < 4; e++) {
                    int row = wm * 32 + mi * 16 + gID + ((e >> 1) << 3);
                    int col = wn * 32 + ni * 8 + t4 * 2 + (e & 1);
                    atomicAdd(&f1a[row * 65 + (col & 63)], freg[mi][ni][e]);
                }
    }
    __syncthreads();

    float* dst = g_f1p + (size_t)blockIdx.y * (BTOT * 64);
    for (int i = tid; i < 64 * 64; i += 320) {
        int r = i >> 6, d = i & 63;
        int b = m0 + r;
        if (b < BTOT) dst[(size_t)b * 64 + d] = f1a[r * 65 + d];
    }
}

// ---------------- LN1: sum NS1 partials, LayerNorm(64)+relu ----------------
__global__ void __launch_bounds__(256, 8) ln1_kernel(
    const float* __restrict__ g1, const float* __restrict__ be1)
{
    int w = threadIdx.x >> 5, lane = threadIdx.x & 31;
    int b = blockIdx.x * 8 + w;
    if (b >= BTOT) return;
    int d = lane * 2;
    float v0 = 0.f, v1 = 0.f;
#pragma unroll
    for (int s = 0; s < NS1; s++) {
        float2 t = *(const float2*)(g_f1p + (size_t)s * (BTOT * 64) + (size_t)b * 64 + d);
        v0 += t.x; v1 += t.y;
    }
    float s1 = v0 + v1, s2 = v0 * v0 + v1 * v1;
#pragma unroll
    for (int o = 16; o; o >>= 1) {
        s1 += __shfl_xor_sync(0xffffffffu, s1, o);
        s2 += __shfl_xor_sync(0xffffffffu, s2, o);
    }
    float mu = s1 * (1.f / 64.f);
    float inv = rsqrtf(s2 * (1.f / 64.f) - mu * mu + 1e-5f);
    float y0 = fmaxf((v0 - mu) * inv * g1[d] + be1[d], 0.f);
    float y1 = fmaxf((v1 - mu) * inv * g1[d + 1] + be1[d + 1], 0.f);
    *(float2*)(g_f1n + (size_t)b * 64 + d) = make_float2(y0, y1);
}

// ---------------- Stage 2: super-staged, 2 producer warps ----------------
// grid (113, 2, NS2): each block does 16 d's -> 32 supers.
__global__ void __launch_bounds__(320, 2) k2_kernel(const float* __restrict__ baft)
{
    extern __shared__ unsigned char sm[];
    uint32_t sb = (uint32_t)__cvta_generic_to_shared(sm);
    const uint32_t A = sb, B = sb + B_OFF;
    const uint32_t MBF = sb + MB_OFF, MBE = sb + MB_OFF + 16;

    const int tid = threadIdx.x, warp = tid >> 5, lane = tid & 31;
    const int m0 = blockIdx.x * 64;
    const int e0 = blockIdx.y << 7;
    const int d0 = blockIdx.z << 4;       // 16 d's per block
    const int G = 32;                     // 16 tiles x 2 supers

    if (tid == 0) {
        mbar_init(MBF, 64); mbar_init(MBF + 8, 64);
        mbar_init(MBE, 8);  mbar_init(MBE + 8, 8);
    }
    if (tid < 256) { load_A(A, g_qh, m0, tid); CP_WAIT0; }
    __syncthreads();

    const int wm = warp >> 2, wn = warp & 3;
    const int gID = lane >> 2, t4 = lane & 3;

    if (warp >= 8) {
        const int pc = warp - 8;
        for (int g = 0; g < G; g++) {
            int s = g & 1;
            if (g >= 2) mbar_wait(MBE + s * 8, ((g >> 1) - 1) & 1);
            int p0 = ((d0 + (g >> 1)) << 8) + e0;
            const __half* Wc = g_wafth + (size_t)p0 * 256 + (g & 1) * 128 + pc * 64;
            issue_chunk_p(B, s, pc, Wc, lane);
            if (g >= 1) { CP_WAIT1; mbar_arrive(MBF + ((g - 1) & 1) * 8); }
        }
        CP_WAIT0; mbar_arrive(MBF + ((G - 1) & 1) * 8);
    } else {
        uint32_t aaddr0, aaddr1, boff;
        frag_addrs(A, wm, wn, lane, aaddr0, aaddr1, boff);
        float facc[2][4][4];
        ZERO_ACC(facc);
        float cacc[2][4][4];
        ZERO_ACC(cacc);
        for (int g = 0; g < G; g++) {
            int s = g & 1;
            mbar_wait(MBF + s * 8, (g >> 1) & 1);
            super_mma(aaddr0, aaddr1, B + (uint32_t)s * SUPER_B, boff,
                      (uint32_t)(g & 1) * 256, cacc, MBE + s * 8, lane);
            if (g & 1) {
                const int t = g >> 1;
                const int d = d0 + t;
                const int p0 = (d << 8) + e0;
                float fv[2][2];
#pragma unroll
                for (int mi = 0; mi < 2; mi++)
#pragma unroll
                    for (int eh = 0; eh < 2; eh++) {
                        int r = m0 + wm * 32 + mi * 16 + gID + (eh << 3);
                        fv[mi][eh] = (r < BTOT) ? __ldg(&g_f1n[(size_t)r * 64 + d]) : 0.f;
                    }
#pragma unroll
                for (int ni = 0; ni < 4; ni++) {
                    int colb = wn * 32 + ni * 8 + t4 * 2;
                    float b0 = __ldg(&baft[p0 + colb]);
                    float b1 = __ldg(&baft[p0 + colb + 1]);
#pragma unroll
                    for (int mi = 0; mi < 2; mi++)
#pragma unroll
                        for (int e = 0; e < 4; e++) {
                            float bias = (e & 1) ? b1 : b0;
                            facc[mi][ni][e] += fv[mi][e >> 1] * (cacc[mi][ni][e] + bias);
                        }
                }
                ZERO_ACC(cacc);
            }
        }
        float* dst = g_f2p + (size_t)blockIdx.z * (BTOT * 256);
#pragma unroll
        for (int mi = 0; mi < 2; mi++)
#pragma unroll
            for (int ni = 0; ni < 4; ni++)
#pragma unroll
                for (int e = 0; e < 4; e++) {
                    int row = wm * 32 + mi * 16 + gID + ((e >> 1) << 3);
                    int col = wn * 32 + ni * 8 + t4 * 2 + (e & 1);
                    int b = m0 + row;
                    if (b < BTOT) dst[(size_t)b * 256 + e0 + col] = facc[mi][ni][e];
                }
    }
}

// ---------------- Stage 3: fused LN2 (A-fill) + GEMM + LN3, dual producers ----
__global__ void __launch_bounds__(320, 1) k3_kernel(
    const float* __restrict__ g2, const float* __restrict__ be2,
    const float* __restrict__ bout,
    const float* __restrict__ g3, const float* __restrict__ be3,
    float* __restrict__ out)
{
    extern __shared__ unsigned char sm[];
    uint32_t sb = (uint32_t)__cvta_generic_to_shared(sm);
    const uint32_t A = sb, B = sb + B_OFF;
    const uint32_t MBF = sb + MB_OFF, MBE = sb + MB_OFF + 16;
    float* f3a = (float*)(sm + F3_OFF);

    const int tid = threadIdx.x, warp = tid >> 5, lane = tid & 31;
    const int m0 = blockIdx.x * 64;
    const int G = 4;     // 2 tiles x 2 supers

    if (tid == 0) {
        mbar_init(MBF, 64); mbar_init(MBF + 8, 64);   // 2 producer warps
        mbar_init(MBE, 8);  mbar_init(MBE + 8, 8);
    }

    // ---- fused LN2: sum NS2 partials -> LN -> fp16 -> A smem ----
    if (warp < 8) {
#pragma unroll
        for (int j = 0; j < 8; j++) {
            int r = warp * 8 + j;
            int b = m0 + r;
            float v[8];
#pragma unroll
            for (int i = 0; i < 8; i++) v[i] = 0.f;
            if (b < BTOT) {
#pragma unroll
                for (int sp = 0; sp < NS2; sp++) {
                    const float4* p = (const float4*)(g_f2p + (size_t)sp * (BTOT * 256)
                                                      + (size_t)b * 256 + lane * 8);
                    float4 x0 = p[0], x1 = p[1];
                    v[0] += x0.x; v[1] += x0.y; v[2] += x0.z; v[3] += x0.w;
                    v[4] += x1.x; v[5] += x1.y; v[6] += x1.z; v[7] += x1.w;
                }
            }
            float s1 = 0.f, s2 = 0.f;
#pragma unroll
            for (int i = 0; i < 8; i++) { s1 += v[i]; s2 += v[i] * v[i]; }
#pragma unroll
            for (int o = 16; o; o >>= 1) {
                s1 += __shfl_xor_sync(0xffffffffu, s1, o);
                s2 += __shfl_xor_sync(0xffffffffu, s2, o);
            }
            float mu = s1 * (1.f / 256.f);
            float inv = rsqrtf(s2 * (1.f / 256.f) - mu * mu + 1e-5f);
            float o_[8];
#pragma unroll
            for (int i = 0; i < 8; i++) {
                int e = lane * 8 + i;
                o_[i] = fmaxf((v[i] - mu) * inv * g2[e] + be2[e], 0.f);
            }
            uint4 pk;
            pk.x = pack_h2(o_[0], o_[1]); pk.y = pack_h2(o_[2], o_[3]);
            pk.z = pack_h2(o_[4], o_[5]); pk.w = pack_h2(o_[6], o_[7]);
            *(uint4*)(sm + r * A_STRIDE + lane * 16) = pk;
        }
    }
    __syncthreads();

    const int wm = warp >> 2, wn = warp & 3;
    const int gID = lane >> 2, t4 = lane & 3;

    if (warp >= 8) {
        const int pc = warp - 8;
        for (int g = 0; g < G; g++) {
            int s = g & 1;
            if (g >= 2) mbar_wait(MBE + s * 8, ((g >> 1) - 1) & 1);
            int p0 = (g >> 1) << 7;
            const __half* Wc = g_wouth + (size_t)p0 * 256 + (g & 1) * 128 + pc * 64;
            issue_chunk_p(B, s, pc, Wc, lane);
            if (g >= 1) { CP_WAIT1; mbar_arrive(MBF + ((g - 1) & 1) * 8); }
        }
        CP_WAIT0; mbar_arrive(MBF + ((G - 1) & 1) * 8);
    } else {
        uint32_t aaddr0, aaddr1, boff;
        frag_addrs(A, wm, wn, lane, aaddr0, aaddr1, boff);
        float cacc[2][4][4];
        ZERO_ACC(cacc);
        for (int g = 0; g < G; g++) {
            int s = g & 1;
            mbar_wait(MBF + s * 8, (g >> 1) & 1);
            super_mma(aaddr0, aaddr1, B + (uint32_t)s * SUPER_B, boff,
                      (uint32_t)(g & 1) * 256, cacc, MBE + s * 8, lane);
            if (g & 1) {
                const int p0 = (g >> 1) << 7;
#pragma unroll
                for (int mi = 0; mi < 2; mi++)
#pragma unroll
                    for (int ni = 0; ni < 4; ni++)
#pragma unroll
                        for (int e = 0; e < 4; e++) {
                            int row = wm * 32 + mi * 16 + gID + ((e >> 1) << 3);
                            int col = wn * 32 + ni * 8 + t4 * 2 + (e & 1);
                            f3a[row * 260 + p0 + col] = cacc[mi][ni][e] + __ldg(&bout[p0 + col]);
                        }
                ZERO_ACC(cacc);
            }
        }
    }
    __syncthreads();

    if (tid < 256) {
        const int row = tid >> 2;
        const int b = m0 + row;
        if (b < BTOT) {
            const int e0 = (tid & 3) * 64;
            float s1 = 0.f, s2 = 0.f;
#pragma unroll
            for (int i = 0; i < 64; i++) {
                float x = f3a[row * 260 + e0 + i];
                s1 += x; s2 += x * x;
            }
            s1 += __shfl_xor_sync(0xffffffffu, s1, 1); s1 += __shfl_xor_sync(0xffffffffu, s1, 2);
            s2 += __shfl_xor_sync(0xffffffffu, s2, 1); s2 += __shfl_xor_sync(0xffffffffu, s2, 2);
            float mu = s1 * (1.f / 256.f);
            float inv = rsqrtf(s2 * (1.f / 256.f) - mu * mu + 1e-5f);
#pragma unroll
            for (int i = 0; i < 64; i++) {
                int e = e0 + i;
                float y = (f3a[row * 260 + e] - mu) * inv * g3[e] + be3[e];
                out[(size_t)b * 256 + e] = fmaxf(y, 0.f);
            }
        }
    }
}

// ---------------- host launch ----------------
extern "C" void kernel_launch(void* const* d_in, const int* in_sizes, int n_in,
                              void* d_out, int out_size)
{
    const float* q     = (const float*)d_in[0];
    const float* feats = (const float*)d_in[1];
    const float* Wpre  = (const float*)d_in[2];
    const float* bpre  = (const float*)d_in[3];
    const float* Waft  = (const float*)d_in[4];
    const float* baft  = (const float*)d_in[5];
    const float* Wout  = (const float*)d_in[6];
    const float* bout  = (const float*)d_in[7];
    const float* g1  = (const float*)d_in[8];
    const float* be1 = (const float*)d_in[9];
    const float* g2  = (const float*)d_in[10];
    const float* be2 = (const float*)d_in[11];
    const float* g3  = (const float*)d_in[12];
    const float* be3 = (const float*)d_in[13];
    float* out = (float*)d_out;

    cudaFuncSetAttribute(k1_kernel, cudaFuncAttributeMaxDynamicSharedMemorySize, SMEM_12);
    cudaFuncSetAttribute(k2_kernel, cudaFuncAttributeMaxDynamicSharedMemorySize, SMEM_12);
    cudaFuncSetAttribute(k3_kernel, cudaFuncAttributeMaxDynamicSharedMemorySize, SMEM_3K);

    // preround: Wpre + Q only
    const size_t nf4 = (size_t)N1 * 64 + (size_t)BTOT * 64;
    int pr_blocks = (int)((nf4 + 255) / 256);

    preround_kernel<<<pr_blocks, 256>>>(q, Wpre);
    k1_kernel<<<dim3(113, NS1 + 1), 320, SMEM_12>>>(feats, bpre, Waft, Wout);
    ln1_kernel<<<dim3(900), 256>>>(g1, be1);
    k2_kernel<<<dim3(113, 2, NS2), 320, SMEM_12>>>(baft);
    k3_kernel<<<dim3(113), 320, SMEM_3K>>>(g2, be2, bout, g3, be3, out);
}